// round 6
// baseline (speedup 1.0000x reference)
#include <cuda_runtime.h>

// IDCT (DCT-III), B=4096 rows, N=4096. Makhoul + Hermitian-packed 2048-pt
// complex inverse FFT per row. 2048 = 16 * 16 * 8, 128 threads, 16 pts/thread.
// Complex values kept as packed 64-bit; butterfly add/sub use Blackwell
// add/sub.rn.f32x2 (one packed op == two scalar FADDs; ptxas never emits these).

#define NN 4096
#define MM 2048
#define THREADS 128
#define SW(m) ((m) ^ (((m) >> 4) & 15))

typedef unsigned long long c64;   // packed complex: lo = re, hi = im

__device__ __forceinline__ c64 mkc(float x, float y) {
    c64 r; asm("mov.b64 %0,{%1,%2};" : "=l"(r) : "f"(x), "f"(y)); return r;
}
__device__ __forceinline__ float2 unc(c64 v) {
    float2 r; asm("mov.b64 {%0,%1},%2;" : "=f"(r.x), "=f"(r.y) : "l"(v)); return r;
}
__device__ __forceinline__ c64 padd(c64 a, c64 b) {
    c64 r; asm("add.rn.f32x2 %0,%1,%2;" : "=l"(r) : "l"(a), "l"(b)); return r;
}
__device__ __forceinline__ c64 psub(c64 a, c64 b) {
    c64 r; asm("sub.rn.f32x2 %0,%1,%2;" : "=l"(r) : "l"(a), "l"(b)); return r;
}
__device__ __forceinline__ c64 pjmul(c64 v) {            // j*v
    float2 d = unc(v); return mkc(-d.y, d.x);
}
__device__ __forceinline__ c64 pcmul(float2 w, c64 v) {  // (scalar complex w) * v
    float2 a = unc(v);
    return mkc(fmaf(w.x, a.x, -w.y * a.y), fmaf(w.x, a.y, w.y * a.x));
}

// scalar float2 complex helpers (twiddle generation)
__device__ __forceinline__ float2 cmul(float2 a, float2 b) {
    return make_float2(fmaf(a.x, b.x, -a.y * b.y), fmaf(a.x, b.y, a.y * b.x));
}
__device__ __forceinline__ float2 csqr(float2 a) {
    return make_float2(fmaf(a.x, a.x, -a.y * a.y), 2.0f * a.x * a.y);
}

// W_2048^{idx/2} = (e^{+j*pi*idx/8192})^4 ; expk[idx] = (cos t, -sin t)
__device__ __forceinline__ float2 tw_from_expk(const float2* __restrict__ expk, int idx) {
    float2 E = __ldg(&expk[idx]);
    float2 e = make_float2(E.x, -E.y);
    e = csqr(e);
    e = csqr(e);
    return e;
}

// Inverse DFT-8 (+j convention), packed.
__device__ __forceinline__ void idft8p(const c64 a[8], c64 X[8]) {
    const float C = 0.70710678118654752f;
    c64 p0 = padd(a[0], a[4]), m0 = psub(a[0], a[4]);
    c64 q0 = padd(a[2], a[6]), r0 = pjmul(psub(a[2], a[6]));
    c64 E0 = padd(p0, q0), E1 = padd(m0, r0), E2 = psub(p0, q0), E3 = psub(m0, r0);
    c64 p1 = padd(a[1], a[5]), m1 = psub(a[1], a[5]);
    c64 q1 = padd(a[3], a[7]), r1 = pjmul(psub(a[3], a[7]));
    c64 O0 = padd(p1, q1), O1 = padd(m1, r1), O2 = psub(p1, q1), O3 = psub(m1, r1);
    float2 o1 = unc(O1), o2 = unc(O2), o3 = unc(O3);
    c64 T1 = mkc(C * (o1.x - o1.y), C * (o1.x + o1.y));      // w8^1 * O1
    c64 T2 = mkc(-o2.y, o2.x);                                // j * O2
    c64 T3 = mkc(-C * (o3.x + o3.y), C * (o3.x - o3.y));     // w8^3 * O3
    X[0] = padd(E0, O0); X[4] = psub(E0, O0);
    X[1] = padd(E1, T1); X[5] = psub(E1, T1);
    X[2] = padd(E2, T2); X[6] = psub(E2, T2);
    X[3] = padd(E3, T3); X[7] = psub(E3, T3);
}

// Inverse DFT-16 (+j), 4x4 split, packed.
__device__ __forceinline__ void idft16p(const c64 a[16], c64 X[16]) {
    const float C8  = 0.70710678118654752f;
    const float C16 = 0.92387953251128674f;
    const float S16 = 0.38268343236508977f;
    c64 B[4][4];
#pragma unroll
    for (int n0 = 0; n0 < 4; n0++) {
        c64 A0 = a[n0], A1 = a[n0 + 4], A2 = a[n0 + 8], A3 = a[n0 + 12];
        c64 s02 = padd(A0, A2), d02 = psub(A0, A2);
        c64 s13 = padd(A1, A3);
        c64 jd13 = pjmul(psub(A1, A3));
        B[n0][0] = padd(s02, s13);
        B[n0][1] = padd(d02, jd13);
        B[n0][2] = psub(s02, s13);
        B[n0][3] = psub(d02, jd13);
    }
    // m0 = 0: trivial twiddles
    {
        c64 C0 = B[0][0], C1 = B[1][0], C2 = B[2][0], C3 = B[3][0];
        c64 s = padd(C0, C2), d = psub(C0, C2);
        c64 t = padd(C1, C3);
        c64 jd = pjmul(psub(C1, C3));
        X[0] = padd(s, t); X[4] = padd(d, jd); X[8] = psub(s, t); X[12] = psub(d, jd);
    }
    // m0 = 1: twiddles 1, W16, W16^2=(C8,C8), W16^3=(S16,C16)
    {
        c64 C0 = B[0][1];
        c64 C1 = pcmul(make_float2(C16, S16), B[1][1]);
        float2 b2 = unc(B[2][1]);
        c64 C2 = mkc(C8 * (b2.x - b2.y), C8 * (b2.x + b2.y));
        c64 C3 = pcmul(make_float2(S16, C16), B[3][1]);
        c64 s = padd(C0, C2), d = psub(C0, C2);
        c64 t = padd(C1, C3);
        c64 jd = pjmul(psub(C1, C3));
        X[1] = padd(s, t); X[5] = padd(d, jd); X[9] = psub(s, t); X[13] = psub(d, jd);
    }
    // m0 = 2: twiddles 1, (C8,C8), j, (-C8,C8)
    {
        c64 C0 = B[0][2];
        float2 b1 = unc(B[1][2]);
        c64 C1 = mkc(C8 * (b1.x - b1.y), C8 * (b1.x + b1.y));
        c64 C2 = pjmul(B[2][2]);
        float2 b3 = unc(B[3][2]);
        c64 C3 = mkc(-C8 * (b3.x + b3.y), C8 * (b3.x - b3.y));
        c64 s = padd(C0, C2), d = psub(C0, C2);
        c64 t = padd(C1, C3);
        c64 jd = pjmul(psub(C1, C3));
        X[2] = padd(s, t); X[6] = padd(d, jd); X[10] = psub(s, t); X[14] = psub(d, jd);
    }
    // m0 = 3: twiddles 1, (S16,C16), (-C8,C8), (-C16,-S16)
    {
        c64 C0 = B[0][3];
        c64 C1 = pcmul(make_float2(S16, C16), B[1][3]);
        float2 b2 = unc(B[2][3]);
        c64 C2 = mkc(-C8 * (b2.x + b2.y), C8 * (b2.x - b2.y));
        float2 b3 = unc(B[3][3]);
        c64 C3 = mkc(-fmaf(C16, b3.x, -S16 * b3.y), -fmaf(C16, b3.y, S16 * b3.x));
        c64 s = padd(C0, C2), d = psub(C0, C2);
        c64 t = padd(C1, C3);
        c64 jd = pjmul(psub(C1, C3));
        X[3] = padd(s, t); X[7] = padd(d, jd); X[11] = psub(s, t); X[15] = psub(d, jd);
    }
}

// Apply w1^i and store out[SW(base + i*S)] (squaring tree keeps chain short).
__device__ __forceinline__ void tw_store16p(c64* __restrict__ out, const c64 X[16],
                                            float2 w1, int base, int S) {
    float2 w2 = csqr(w1);
    float2 w4 = csqr(w2);
    float2 w8 = csqr(w4);
    float2 w3 = cmul(w1, w2);
    float2 w5 = cmul(w1, w4);
    float2 w6 = cmul(w2, w4);
    float2 w7 = cmul(w3, w4);
    out[SW(base)]          = X[0];
    out[SW(base + S)]      = pcmul(w1, X[1]);
    out[SW(base + 2 * S)]  = pcmul(w2, X[2]);
    out[SW(base + 3 * S)]  = pcmul(w3, X[3]);
    out[SW(base + 4 * S)]  = pcmul(w4, X[4]);
    out[SW(base + 5 * S)]  = pcmul(w5, X[5]);
    out[SW(base + 6 * S)]  = pcmul(w6, X[6]);
    out[SW(base + 7 * S)]  = pcmul(w7, X[7]);
    out[SW(base + 8 * S)]  = pcmul(w8, X[8]);
    out[SW(base + 9 * S)]  = pcmul(cmul(w1, w8), X[9]);
    out[SW(base + 10 * S)] = pcmul(cmul(w2, w8), X[10]);
    out[SW(base + 11 * S)] = pcmul(cmul(w3, w8), X[11]);
    out[SW(base + 12 * S)] = pcmul(cmul(w4, w8), X[12]);
    out[SW(base + 13 * S)] = pcmul(cmul(w5, w8), X[13]);
    out[SW(base + 14 * S)] = pcmul(cmul(w6, w8), X[14]);
    out[SW(base + 15 * S)] = pcmul(cmul(w7, w8), X[15]);
}

__global__ __launch_bounds__(THREADS, 9)
void idct_kernel(const float* __restrict__ x,
                 const float2* __restrict__ expk,
                 float* __restrict__ y) {
    extern __shared__ c64 buf[];   // 2048 packed complex, in-place via syncs

    const int tid = threadIdx.x;
    const float* xr = x + (size_t)blockIdx.x * NN;
    const float C8 = 0.70710678118654752f;

    // ---- Z build (direct global reads) + radix-16 stage 1 (S=1, p=tid) ----
    {
        c64 Z[16];
#pragma unroll
        for (int i = 0; i < 16; i++) {
            int k = tid + i * THREADS;
            float xk   = xr[k];
            float xnk  = (k == 0) ? 0.0f : xr[NN - k];
            float xmk  = xr[MM - k];
            float xmpk = xr[MM + k];
            float2 E1 = __ldg(&expk[k]);         // (cos t, -sin t), t = pi*k/8192
            float c1 = E1.x, s1 = -E1.y;
            // e^{j*pi*(2048-k)/8192} = e^{j*pi/4} * conj(e^{j*pi*k/8192})
            float c2 = C8 * (c1 + s1), s2 = C8 * (c1 - s1);
            float2 Vk = make_float2(fmaf(xk, c1, xnk * s1), fmaf(xk, s1, -xnk * c1));
            float2 Vm = make_float2(fmaf(xmk, c2, xmpk * s2), fmaf(xmk, s2, -xmpk * c2));
            float2 P = make_float2(Vk.x + Vm.x, Vk.y - Vm.y);   // V_k + conj(V_{M-k})
            float2 Q = make_float2(Vk.x - Vm.x, Vk.y + Vm.y);   // V_k - conj(V_{M-k})
            float2 W = csqr(csqr(make_float2(c1, s1)));          // e^{j*2pi*k/4096}
            Z[i] = mkc(P.x - W.y * Q.x - W.x * Q.y,
                       P.y + W.x * Q.x - W.y * Q.y);
        }
        c64 X[16];
        idft16p(Z, X);
        float2 w1 = tw_from_expk(expk, 2 * tid);   // W_2048^{tid}
        tw_store16p(buf, X, w1, 16 * tid, 1);
    }
    __syncthreads();

    // ---- radix-16 stage 2 (S=16): in-place (regs -> sync -> write) ----
    {
        c64 a[16], X[16];
#pragma unroll
        for (int i = 0; i < 16; i++) a[i] = buf[SW(tid + 128 * i)];
        idft16p(a, X);
        int p = tid >> 4, q = tid & 15;
        float2 w1 = tw_from_expk(expk, 32 * p);    // W_2048^{16p}
        __syncthreads();                            // all reads done before writes
        tw_store16p(buf, X, w1, q + 256 * p, 16);
    }
    __syncthreads();

    // ---- radix-8 stage 3 (S=256, trivial twiddle) fused with output perm ----
    // Thread handles butterflies b1=tid, b2=255-tid: partner of z_{q+256i}
    // is z_{2047-(q+256i)} = z_{(255-q)+256(7-i)} -> thread-local.
    {
        const int b1 = tid, b2 = 255 - tid;
        c64 a1[8], a2[8], z1[8], z2[8];
#pragma unroll
        for (int i = 0; i < 8; i++) a1[i] = buf[SW(b1 + 256 * i)];
#pragma unroll
        for (int i = 0; i < 8; i++) a2[i] = buf[SW(b2 + 256 * i)];
        idft8p(a1, z1);
        idft8p(a2, z2);
        // y[4s..4s+3] = {Re z_s, Im z_{2047-s}, Im z_s, Re z_{2047-s}}
        float4* yr = (float4*)(y + (size_t)blockIdx.x * NN);
#pragma unroll
        for (int i = 0; i < 4; i++) {
            float2 u1 = unc(z1[i]), u2 = unc(z2[7 - i]);
            float2 v2 = unc(z2[i]), v1 = unc(z1[7 - i]);
            yr[b1 + 256 * i] = make_float4(u1.x, u2.y, u1.y, u2.x);
            yr[b2 + 256 * i] = make_float4(v2.x, v1.y, v2.y, v1.x);
        }
    }
}

extern "C" void kernel_launch(void* const* d_in, const int* in_sizes, int n_in,
                              void* d_out, int out_size) {
    const float*  x    = (const float*)d_in[0];
    const float2* expk = (const float2*)d_in[1];
    float*        y    = (float*)d_out;

    int rows = in_sizes[0] / NN;             // 4096
    size_t smem_bytes = MM * sizeof(c64);    // 16 KB, single in-place buffer
    idct_kernel<<<rows, THREADS, smem_bytes>>>(x, expk, y);
}